// round 1
// baseline (speedup 1.0000x reference)
#include <cuda_runtime.h>

#define NMAX 100000
#define EMAX 1600000

// ---------------- device scratch (no allocations allowed) ----------------
__device__ int   g_deg[NMAX];
__device__ int   g_cursor[NMAX];
__device__ int   g_rowptr[NMAX + 1];
__device__ float g_deginv[NMAX];
__device__ unsigned char g_flag[NMAX];          // 0 none, 1 keep, 2 low
__device__ int   g_esrc[EMAX];                  // src ids binned by dst (CSR)
__device__ float g_XY1[(size_t)NMAX * 256];     // [X@W1_self + b1 | X@W1_neigh]
__device__ float g_h1 [(size_t)NMAX * 128];     // relu layer-1 output
__device__ float g_Y  [(size_t)NMAX * 128];     // [h1@W2_self + b2 | h1@W2_neigh]
__device__ float g_W1 [128 * 256];              // cat(W1_self, W1_neigh)
__device__ float g_W2 [128 * 128];              // cat(W2_self, W2_neigh)
__device__ float g_b1 [256];                    // cat(b1, 0)
__device__ float g_b2 [128];                    // cat(b2, 0)

// ---------------- small prep kernels ----------------
__global__ void k_zero(int N) {
    int i = blockIdx.x * blockDim.x + threadIdx.x;
    if (i < N) { g_deg[i] = 0; g_cursor[i] = 0; g_flag[i] = 0; }
}

__global__ void k_prep(const float* __restrict__ W1s, const float* __restrict__ W1n,
                       const float* __restrict__ b1,
                       const float* __restrict__ W2s, const float* __restrict__ W2n,
                       const float* __restrict__ b2) {
    int i = blockIdx.x * blockDim.x + threadIdx.x;
    if (i < 128 * 256) {
        int k = i >> 8, j = i & 255;
        g_W1[i] = (j < 128) ? W1s[k * 128 + j] : W1n[k * 128 + (j - 128)];
    }
    int i2 = i - 128 * 256;
    if (i2 >= 0 && i2 < 128 * 128) {
        int k = i2 >> 7, j = i2 & 127;
        g_W2[i2] = (j < 64) ? W2s[k * 64 + j] : W2n[k * 64 + (j - 64)];
    }
    if (i < 256) g_b1[i] = (i < 128) ? b1[i] : 0.f;
    if (i < 128) g_b2[i] = (i < 64) ? b2[i] : 0.f;
}

__global__ void k_flags(const int* __restrict__ keep, int nk,
                        const int* __restrict__ low, int nl) {
    int i = blockIdx.x * blockDim.x + threadIdx.x;
    if (i < nk) g_flag[keep[i]] = 1;
    else if (i - nk < nl) g_flag[low[i - nk]] = 2;
}

__global__ void k_degcount(const int* __restrict__ dst, int E) {
    int i = blockIdx.x * blockDim.x + threadIdx.x;
    if (i < E) atomicAdd(&g_deg[dst[i]], 1);
}

// single-block scan over degrees -> rowptr, and deg_inv
__global__ void k_scan(int N, int E) {
    __shared__ int part[1024];
    int t = threadIdx.x;
    int chunk = (N + 1023) >> 10;
    int lo = t * chunk;
    int hi = lo + chunk; if (hi > N) hi = N; if (lo > N) lo = N;
    int s = 0;
    for (int i = lo; i < hi; i++) s += g_deg[i];
    part[t] = s;
    __syncthreads();
    for (int off = 1; off < 1024; off <<= 1) {
        int v = 0;
        if (t >= off) v = part[t - off];
        __syncthreads();
        if (t >= off) part[t] += v;
        __syncthreads();
    }
    int run = (t == 0) ? 0 : part[t - 1];
    for (int i = lo; i < hi; i++) {
        g_rowptr[i] = run;
        int c = g_deg[i];
        g_deginv[i] = 1.0f / (float)((c > 1) ? c : 1);
        run += c;
    }
    if (t == 0) g_rowptr[N] = E;
}

__global__ void k_bin(const int* __restrict__ src, const int* __restrict__ dst, int E) {
    int i = blockIdx.x * blockDim.x + threadIdx.x;
    if (i < E) {
        int d = dst[i];
        int p = atomicAdd(&g_cursor[d], 1);
        g_esrc[g_rowptr[d] + p] = src[i];
    }
}

// ---------------- fp32 tiled GEMM: Y[M x NCOLS] = X[M x 128] @ W + bias ----------------
// NCOLS==256: X = external features, W = g_W1, Y = g_XY1
// NCOLS==128: X = g_h1,             W = g_W2, Y = g_Y
template <int NCOLS>
__global__ void k_gemm(const float* __restrict__ Xext, int M) {
    extern __shared__ float sm[];
    float* As = sm;            // 64 x 128 (row-major)
    float* Bs = sm + 64 * 128; // 128 x 64 (k-major)
    const float* X    = (NCOLS == 256) ? Xext : g_h1;
    const float* W    = (NCOLS == 256) ? g_W1 : g_W2;
    const float* bias = (NCOLS == 256) ? g_b1 : g_b2;
    float* Y          = (NCOLS == 256) ? g_XY1 : g_Y;

    int bm = blockIdx.y * 64, bn = blockIdx.x * 64;
    int tid = threadIdx.x;

    #pragma unroll 4
    for (int i = tid; i < 64 * 128; i += 256) {
        int r = i >> 7, k = i & 127;
        int row = bm + r;
        As[i] = (row < M) ? X[row * 128 + k] : 0.f;
    }
    #pragma unroll 4
    for (int i = tid; i < 128 * 64; i += 256) {
        int k = i >> 6, n = i & 63;
        Bs[i] = W[k * NCOLS + bn + n];
    }
    __syncthreads();

    int tx = tid & 15, ty = tid >> 4;
    int m0 = ty << 2, n0 = tx << 2;
    float acc[4][4];
    #pragma unroll
    for (int q = 0; q < 4; q++)
        #pragma unroll
        for (int r = 0; r < 4; r++) acc[q][r] = 0.f;

    const float* a0p = &As[m0 * 128];
    #pragma unroll 8
    for (int k = 0; k < 128; k++) {
        float4 b = *(const float4*)(Bs + k * 64 + n0);
        float a0 = a0p[k];
        float a1 = a0p[128 + k];
        float a2 = a0p[256 + k];
        float a3 = a0p[384 + k];
        acc[0][0] = fmaf(a0, b.x, acc[0][0]); acc[0][1] = fmaf(a0, b.y, acc[0][1]);
        acc[0][2] = fmaf(a0, b.z, acc[0][2]); acc[0][3] = fmaf(a0, b.w, acc[0][3]);
        acc[1][0] = fmaf(a1, b.x, acc[1][0]); acc[1][1] = fmaf(a1, b.y, acc[1][1]);
        acc[1][2] = fmaf(a1, b.z, acc[1][2]); acc[1][3] = fmaf(a1, b.w, acc[1][3]);
        acc[2][0] = fmaf(a2, b.x, acc[2][0]); acc[2][1] = fmaf(a2, b.y, acc[2][1]);
        acc[2][2] = fmaf(a2, b.z, acc[2][2]); acc[2][3] = fmaf(a2, b.w, acc[2][3]);
        acc[3][0] = fmaf(a3, b.x, acc[3][0]); acc[3][1] = fmaf(a3, b.y, acc[3][1]);
        acc[3][2] = fmaf(a3, b.z, acc[3][2]); acc[3][3] = fmaf(a3, b.w, acc[3][3]);
    }

    float4 bv = *(const float4*)&bias[bn + n0];
    #pragma unroll
    for (int q = 0; q < 4; q++) {
        int row = bm + m0 + q;
        if (row < M) {
            float4 o;
            o.x = acc[q][0] + bv.x; o.y = acc[q][1] + bv.y;
            o.z = acc[q][2] + bv.z; o.w = acc[q][3] + bv.w;
            *(float4*)&Y[(size_t)row * NCOLS + bn + n0] = o;
        }
    }
}

// ---------------- layer-1 aggregation: warp per node ----------------
// h1[i] = relu( XY1[i, :128] + deg_inv[i] * sum_{e: dst=i} XY1[src_e, 128:256] )
__global__ void k_agg1(int N) {
    int w = (blockIdx.x * blockDim.x + threadIdx.x) >> 5;
    int lane = threadIdx.x & 31;
    if (w >= N) return;
    int beg = g_rowptr[w], end = g_rowptr[w + 1];
    float ax = 0.f, ay = 0.f, az = 0.f, aw = 0.f;
    int col = 128 + lane * 4;
    int j = beg;
    for (; j + 1 < end; j += 2) {
        int s0 = g_esrc[j], s1 = g_esrc[j + 1];
        float4 v0 = *(const float4*)&g_XY1[s0 * 256 + col];
        float4 v1 = *(const float4*)&g_XY1[s1 * 256 + col];
        ax += v0.x + v1.x; ay += v0.y + v1.y;
        az += v0.z + v1.z; aw += v0.w + v1.w;
    }
    if (j < end) {
        int s0 = g_esrc[j];
        float4 v0 = *(const float4*)&g_XY1[s0 * 256 + col];
        ax += v0.x; ay += v0.y; az += v0.z; aw += v0.w;
    }
    float di = g_deginv[w];
    float4 xs = *(const float4*)&g_XY1[w * 256 + lane * 4];
    float4 h;
    h.x = fmaxf(fmaf(ax, di, xs.x), 0.f);
    h.y = fmaxf(fmaf(ay, di, xs.y), 0.f);
    h.z = fmaxf(fmaf(az, di, xs.z), 0.f);
    h.w = fmaxf(fmaf(aw, di, xs.w), 0.f);
    *(float4*)&g_h1[w * 128 + lane * 4] = h;
}

// ---------------- layer-2 aggregation + final select: warp per node ----------------
__global__ void k_final(const float* __restrict__ emb, float* __restrict__ out, int N) {
    int w = (blockIdx.x * blockDim.x + threadIdx.x) >> 5;
    int lane = threadIdx.x & 31;
    if (w >= N) return;
    unsigned char f = g_flag[w];
    if (f == 1) {   // keep: pure embedding copy, skip all layer-2 work
        float2 e = *(const float2*)&emb[(size_t)w * 64 + lane * 2];
        *(float2*)&out[(size_t)w * 64 + lane * 2] = e;
        return;
    }
    int beg = g_rowptr[w], end = g_rowptr[w + 1];
    float ax = 0.f, ay = 0.f;
    int col = 64 + lane * 2;
    int j = beg;
    for (; j + 1 < end; j += 2) {
        int s0 = g_esrc[j], s1 = g_esrc[j + 1];
        float2 v0 = *(const float2*)&g_Y[s0 * 128 + col];
        float2 v1 = *(const float2*)&g_Y[s1 * 128 + col];
        ax += v0.x + v1.x; ay += v0.y + v1.y;
    }
    if (j < end) {
        int s0 = g_esrc[j];
        float2 v0 = *(const float2*)&g_Y[s0 * 128 + col];
        ax += v0.x; ay += v0.y;
    }
    float di = g_deginv[w];
    float2 ys = *(const float2*)&g_Y[w * 128 + lane * 2];
    float sc = (f == 2) ? 2.f : 1.f;
    float2 o;
    o.x = (ys.x + ax * di) * sc;
    o.y = (ys.y + ay * di) * sc;
    *(float2*)&out[(size_t)w * 64 + lane * 2] = o;
}

// ---------------- launch ----------------
extern "C" void kernel_launch(void* const* d_in, const int* in_sizes, int n_in,
                              void* d_out, int out_size) {
    const float* features = (const float*)d_in[0];
    const float* W1s = (const float*)d_in[1];
    const float* W1n = (const float*)d_in[2];
    const float* b1  = (const float*)d_in[3];
    const float* W2s = (const float*)d_in[4];
    const float* W2n = (const float*)d_in[5];
    const float* b2  = (const float*)d_in[6];
    const float* emb = (const float*)d_in[7];
    const int* src   = (const int*)d_in[8];
    const int* dst   = (const int*)d_in[9];
    const int* keep  = (const int*)d_in[10];
    const int* low   = (const int*)d_in[11];

    int N  = in_sizes[0] / 128;
    int E  = in_sizes[8];
    int nk = in_sizes[10];
    int nl = in_sizes[11];
    float* out = (float*)d_out;

    cudaFuncSetAttribute(k_gemm<256>, cudaFuncAttributeMaxDynamicSharedMemorySize, 65536);
    cudaFuncSetAttribute(k_gemm<128>, cudaFuncAttributeMaxDynamicSharedMemorySize, 65536);

    k_zero<<<(N + 255) / 256, 256>>>(N);
    k_prep<<<(128 * 256 + 128 * 128 + 255) / 256, 256>>>(W1s, W1n, b1, W2s, W2n, b2);
    k_flags<<<(nk + nl + 255) / 256, 256>>>(keep, nk, low, nl);
    k_degcount<<<(E + 255) / 256, 256>>>(dst, E);
    k_scan<<<1, 1024>>>(N, E);
    k_bin<<<(E + 255) / 256, 256>>>(src, dst, E);

    dim3 g1(256 / 64, (N + 63) / 64);
    k_gemm<256><<<g1, 256, 65536>>>(features, N);

    k_agg1<<<(N + 7) / 8, 256>>>(N);

    dim3 g2(128 / 64, (N + 63) / 64);
    k_gemm<128><<<g2, 256, 65536>>>(nullptr, N);

    k_final<<<(N + 7) / 8, 256>>>(emb, out, N);
}

// round 2
// speedup vs baseline: 1.4177x; 1.4177x over previous
#include <cuda_runtime.h>
#include <cstdint>

#define NMAX 100000
#define EMAX 1600000

// ---------------- device scratch (no allocations allowed) ----------------
__device__ int   g_deg[NMAX];
__device__ int   g_cursor[NMAX];
__device__ int   g_rowptr[NMAX + 1];
__device__ float g_deginv[NMAX];
__device__ unsigned char g_flag[NMAX];          // 0 none, 1 keep, 2 low
__device__ int   g_esrc[EMAX];                  // src ids binned by dst (CSR)
__device__ float g_XY1[(size_t)NMAX * 256];     // [X@W1_self + b1 | X@W1_neigh]
__device__ float g_h1 [(size_t)NMAX * 128];     // relu layer-1 output
__device__ float g_Y  [(size_t)NMAX * 128];     // [h1@W2_self + b2 | h1@W2_neigh]
__device__ float g_W1 [128 * 256];              // cat(W1_self, W1_neigh)
__device__ float g_W2 [128 * 128];              // cat(W2_self, W2_neigh)
__device__ float g_b1 [256];                    // cat(b1, 0)
__device__ float g_b2 [128];                    // cat(b2, 0)

// ---------------- small prep kernels ----------------
__global__ void k_zero(int N) {
    int i = blockIdx.x * blockDim.x + threadIdx.x;
    if (i < N) { g_deg[i] = 0; g_cursor[i] = 0; g_flag[i] = 0; }
}

__global__ void k_prep(const float* __restrict__ W1s, const float* __restrict__ W1n,
                       const float* __restrict__ b1,
                       const float* __restrict__ W2s, const float* __restrict__ W2n,
                       const float* __restrict__ b2) {
    int i = blockIdx.x * blockDim.x + threadIdx.x;
    if (i < 128 * 256) {
        int k = i >> 8, j = i & 255;
        g_W1[i] = (j < 128) ? W1s[k * 128 + j] : W1n[k * 128 + (j - 128)];
    }
    int i2 = i - 128 * 256;
    if (i2 >= 0 && i2 < 128 * 128) {
        int k = i2 >> 7, j = i2 & 127;
        g_W2[i2] = (j < 64) ? W2s[k * 64 + j] : W2n[k * 64 + (j - 64)];
    }
    if (i < 256) g_b1[i] = (i < 128) ? b1[i] : 0.f;
    if (i < 128) g_b2[i] = (i < 64) ? b2[i] : 0.f;
}

__global__ void k_flags(const int* __restrict__ keep, int nk,
                        const int* __restrict__ low, int nl) {
    int i = blockIdx.x * blockDim.x + threadIdx.x;
    if (i < nk) g_flag[keep[i]] = 1;
    else if (i - nk < nl) g_flag[low[i - nk]] = 2;
}

__global__ void k_degcount(const int* __restrict__ dst, int E) {
    int i = blockIdx.x * blockDim.x + threadIdx.x;
    if (i < E) atomicAdd(&g_deg[dst[i]], 1);
}

// single-block scan over degrees -> rowptr, and deg_inv
__global__ void k_scan(int N, int E) {
    __shared__ int part[1024];
    int t = threadIdx.x;
    int chunk = (N + 1023) >> 10;
    int lo = t * chunk;
    int hi = lo + chunk; if (hi > N) hi = N; if (lo > N) lo = N;
    int s = 0;
    for (int i = lo; i < hi; i++) s += g_deg[i];
    part[t] = s;
    __syncthreads();
    for (int off = 1; off < 1024; off <<= 1) {
        int v = 0;
        if (t >= off) v = part[t - off];
        __syncthreads();
        if (t >= off) part[t] += v;
        __syncthreads();
    }
    int run = (t == 0) ? 0 : part[t - 1];
    for (int i = lo; i < hi; i++) {
        g_rowptr[i] = run;
        int c = g_deg[i];
        g_deginv[i] = 1.0f / (float)((c > 1) ? c : 1);
        run += c;
    }
    if (t == 0) g_rowptr[N] = E;
}

__global__ void k_bin(const int* __restrict__ src, const int* __restrict__ dst, int E) {
    int i = blockIdx.x * blockDim.x + threadIdx.x;
    if (i < E) {
        int d = dst[i];
        int p = atomicAdd(&g_cursor[d], 1);
        g_esrc[g_rowptr[d] + p] = src[i];
    }
}

// ---------------- tf32 tensor-core GEMM ----------------
// Y[M x NCOLS] = X[M x 128] @ W[128 x NCOLS] + bias
// Block tile 64x64, full K=128 in smem, 4 warps of 32x32, mma.m16n8k8.tf32.
#define AS_STRIDE 132   // 128 + 4  -> bank = (4g + t) mod 32, conflict-free
#define BS_STRIDE 72    // 64 + 8   -> bank = (8t + g) mod 32, conflict-free

__device__ __forceinline__ uint32_t f2tf32(float f) {
    uint32_t r;
    asm("cvt.rna.tf32.f32 %0, %1;" : "=r"(r) : "f"(f));
    return r;
}

template <int NCOLS>
__global__ void __launch_bounds__(128, 3) k_gemm_tc(const float* __restrict__ Xext, int M) {
    extern __shared__ uint32_t sm[];
    uint32_t* As = sm;                       // 64 x AS_STRIDE (tf32 bits)
    uint32_t* Bs = sm + 64 * AS_STRIDE;      // 128 x BS_STRIDE (tf32 bits)
    const float* X    = (NCOLS == 256) ? Xext : g_h1;
    const float* W    = (NCOLS == 256) ? g_W1 : g_W2;
    const float* bias = (NCOLS == 256) ? g_b1 : g_b2;
    float* Y          = (NCOLS == 256) ? g_XY1 : g_Y;

    int bm = blockIdx.y * 64, bn = blockIdx.x * 64;
    int tid = threadIdx.x;
    int wid = tid >> 5, lane = tid & 31;
    int g = lane >> 2, t = lane & 3;
    int wm = wid >> 1, wn = wid & 1;         // 2x2 warp grid over 64x64

    // stage A: 64 rows x 128 cols -> 2048 float4 chunks, 16 per thread
    #pragma unroll
    for (int i = 0; i < 16; i++) {
        int idx = tid + i * 128;             // 0..2047
        int r = idx >> 5, c4 = (idx & 31) << 2;
        int row = bm + r;
        float4 v = (row < M) ? *(const float4*)&X[(size_t)row * 128 + c4]
                             : make_float4(0.f, 0.f, 0.f, 0.f);
        uint32_t* d = &As[r * AS_STRIDE + c4];
        d[0] = f2tf32(v.x); d[1] = f2tf32(v.y); d[2] = f2tf32(v.z); d[3] = f2tf32(v.w);
    }
    // stage B: 128 rows x 64 cols -> 2048 float4 chunks
    #pragma unroll
    for (int i = 0; i < 16; i++) {
        int idx = tid + i * 128;
        int k = idx >> 4, c4 = (idx & 15) << 2;
        float4 v = *(const float4*)&W[k * NCOLS + bn + c4];
        uint32_t* d = &Bs[k * BS_STRIDE + c4];
        d[0] = f2tf32(v.x); d[1] = f2tf32(v.y); d[2] = f2tf32(v.z); d[3] = f2tf32(v.w);
    }
    __syncthreads();

    float c[2][4][4];
    #pragma unroll
    for (int mt = 0; mt < 2; mt++)
        #pragma unroll
        for (int nt = 0; nt < 4; nt++)
            #pragma unroll
            for (int q = 0; q < 4; q++) c[mt][nt][q] = 0.f;

    #pragma unroll 4
    for (int k0 = 0; k0 < 128; k0 += 8) {
        uint32_t a[2][4];
        #pragma unroll
        for (int mt = 0; mt < 2; mt++) {
            int rb = (wm * 32 + mt * 16 + g) * AS_STRIDE;
            a[mt][0] = As[rb + k0 + t];
            a[mt][1] = As[rb + 8 * AS_STRIDE + k0 + t];
            a[mt][2] = As[rb + k0 + t + 4];
            a[mt][3] = As[rb + 8 * AS_STRIDE + k0 + t + 4];
        }
        uint32_t b[4][2];
        #pragma unroll
        for (int nt = 0; nt < 4; nt++) {
            int col = wn * 32 + nt * 8 + g;
            b[nt][0] = Bs[(k0 + t) * BS_STRIDE + col];
            b[nt][1] = Bs[(k0 + t + 4) * BS_STRIDE + col];
        }
        #pragma unroll
        for (int mt = 0; mt < 2; mt++)
            #pragma unroll
            for (int nt = 0; nt < 4; nt++) {
                asm volatile(
                    "mma.sync.aligned.m16n8k8.row.col.f32.tf32.tf32.f32 "
                    "{%0,%1,%2,%3}, {%4,%5,%6,%7}, {%8,%9}, {%0,%1,%2,%3};"
                    : "+f"(c[mt][nt][0]), "+f"(c[mt][nt][1]),
                      "+f"(c[mt][nt][2]), "+f"(c[mt][nt][3])
                    : "r"(a[mt][0]), "r"(a[mt][1]), "r"(a[mt][2]), "r"(a[mt][3]),
                      "r"(b[nt][0]), "r"(b[nt][1]));
            }
    }

    // epilogue: c0,c1 -> (row, col..col+1), c2,c3 -> (row+8, col..col+1)
    #pragma unroll
    for (int mt = 0; mt < 2; mt++) {
        int row = bm + wm * 32 + mt * 16 + g;
        #pragma unroll
        for (int nt = 0; nt < 4; nt++) {
            int col = bn + wn * 32 + nt * 8 + 2 * t;
            float2 bv = *(const float2*)&bias[col];
            if (row < M) {
                float2 o0 = make_float2(c[mt][nt][0] + bv.x, c[mt][nt][1] + bv.y);
                *(float2*)&Y[(size_t)row * NCOLS + col] = o0;
            }
            if (row + 8 < M) {
                float2 o1 = make_float2(c[mt][nt][2] + bv.x, c[mt][nt][3] + bv.y);
                *(float2*)&Y[(size_t)(row + 8) * NCOLS + col] = o1;
            }
        }
    }
}

// ---------------- layer-1 aggregation: warp per node ----------------
__global__ void k_agg1(int N) {
    int w = (blockIdx.x * blockDim.x + threadIdx.x) >> 5;
    int lane = threadIdx.x & 31;
    if (w >= N) return;
    int beg = g_rowptr[w], end = g_rowptr[w + 1];
    float ax = 0.f, ay = 0.f, az = 0.f, aw = 0.f;
    int col = 128 + lane * 4;
    int j = beg;
    for (; j + 1 < end; j += 2) {
        int s0 = g_esrc[j], s1 = g_esrc[j + 1];
        float4 v0 = *(const float4*)&g_XY1[s0 * 256 + col];
        float4 v1 = *(const float4*)&g_XY1[s1 * 256 + col];
        ax += v0.x + v1.x; ay += v0.y + v1.y;
        az += v0.z + v1.z; aw += v0.w + v1.w;
    }
    if (j < end) {
        int s0 = g_esrc[j];
        float4 v0 = *(const float4*)&g_XY1[s0 * 256 + col];
        ax += v0.x; ay += v0.y; az += v0.z; aw += v0.w;
    }
    float di = g_deginv[w];
    float4 xs = *(const float4*)&g_XY1[w * 256 + lane * 4];
    float4 h;
    h.x = fmaxf(fmaf(ax, di, xs.x), 0.f);
    h.y = fmaxf(fmaf(ay, di, xs.y), 0.f);
    h.z = fmaxf(fmaf(az, di, xs.z), 0.f);
    h.w = fmaxf(fmaf(aw, di, xs.w), 0.f);
    *(float4*)&g_h1[w * 128 + lane * 4] = h;
}

// ---------------- layer-2 aggregation + final select: warp per node ----------------
__global__ void k_final(const float* __restrict__ emb, float* __restrict__ out, int N) {
    int w = (blockIdx.x * blockDim.x + threadIdx.x) >> 5;
    int lane = threadIdx.x & 31;
    if (w >= N) return;
    unsigned char f = g_flag[w];
    if (f == 1) {   // keep: pure embedding copy, skip all layer-2 work
        float2 e = *(const float2*)&emb[(size_t)w * 64 + lane * 2];
        *(float2*)&out[(size_t)w * 64 + lane * 2] = e;
        return;
    }
    int beg = g_rowptr[w], end = g_rowptr[w + 1];
    float ax = 0.f, ay = 0.f;
    int col = 64 + lane * 2;
    int j = beg;
    for (; j + 1 < end; j += 2) {
        int s0 = g_esrc[j], s1 = g_esrc[j + 1];
        float2 v0 = *(const float2*)&g_Y[s0 * 128 + col];
        float2 v1 = *(const float2*)&g_Y[s1 * 128 + col];
        ax += v0.x + v1.x; ay += v0.y + v1.y;
    }
    if (j < end) {
        int s0 = g_esrc[j];
        float2 v0 = *(const float2*)&g_Y[s0 * 128 + col];
        ax += v0.x; ay += v0.y;
    }
    float di = g_deginv[w];
    float2 ys = *(const float2*)&g_Y[w * 128 + lane * 2];
    float sc = (f == 2) ? 2.f : 1.f;
    float2 o;
    o.x = (ys.x + ax * di) * sc;
    o.y = (ys.y + ay * di) * sc;
    *(float2*)&out[(size_t)w * 64 + lane * 2] = o;
}

// ---------------- launch ----------------
extern "C" void kernel_launch(void* const* d_in, const int* in_sizes, int n_in,
                              void* d_out, int out_size) {
    const float* features = (const float*)d_in[0];
    const float* W1s = (const float*)d_in[1];
    const float* W1n = (const float*)d_in[2];
    const float* b1  = (const float*)d_in[3];
    const float* W2s = (const float*)d_in[4];
    const float* W2n = (const float*)d_in[5];
    const float* b2  = (const float*)d_in[6];
    const float* emb = (const float*)d_in[7];
    const int* src   = (const int*)d_in[8];
    const int* dst   = (const int*)d_in[9];
    const int* keep  = (const int*)d_in[10];
    const int* low   = (const int*)d_in[11];

    int N  = in_sizes[0] / 128;
    int E  = in_sizes[8];
    int nk = in_sizes[10];
    int nl = in_sizes[11];
    float* out = (float*)d_out;

    const int smem_bytes = (64 * AS_STRIDE + 128 * BS_STRIDE) * 4;  // 70656
    cudaFuncSetAttribute(k_gemm_tc<256>, cudaFuncAttributeMaxDynamicSharedMemorySize, smem_bytes);
    cudaFuncSetAttribute(k_gemm_tc<128>, cudaFuncAttributeMaxDynamicSharedMemorySize, smem_bytes);

    k_zero<<<(N + 255) / 256, 256>>>(N);
    k_prep<<<(128 * 256 + 128 * 128 + 255) / 256, 256>>>(W1s, W1n, b1, W2s, W2n, b2);
    k_flags<<<(nk + nl + 255) / 256, 256>>>(keep, nk, low, nl);
    k_degcount<<<(E + 255) / 256, 256>>>(dst, E);
    k_scan<<<1, 1024>>>(N, E);
    k_bin<<<(E + 255) / 256, 256>>>(src, dst, E);

    dim3 g1(256 / 64, (N + 63) / 64);
    k_gemm_tc<256><<<g1, 128, smem_bytes>>>(features, N);

    k_agg1<<<(N + 7) / 8, 256>>>(N);

    dim3 g2(128 / 64, (N + 63) / 64);
    k_gemm_tc<128><<<g2, 128, smem_bytes>>>(nullptr, N);

    k_final<<<(N + 7) / 8, 256>>>(emb, out, N);
}

// round 3
// speedup vs baseline: 2.3375x; 1.6488x over previous
#include <cuda_runtime.h>
#include <cstdint>

#define NMAX 100000
#define EMAX 1600000

// ---------------- device scratch (no allocations allowed) ----------------
__device__ int   g_deg[NMAX];
__device__ int   g_cursor[NMAX];
__device__ int   g_rowptr[NMAX + 1];
__device__ int   g_part[128];
__device__ float g_deginv[NMAX];
__device__ unsigned char g_flag[NMAX];          // 0 none, 1 keep, 2 low
__device__ int   g_esrc[EMAX];                  // src ids binned by dst (CSR)
__device__ float g_XY1[(size_t)NMAX * 256];     // [X@W1_self + b1 | X@W1_neigh]
__device__ float g_h1 [(size_t)NMAX * 128];     // relu layer-1 output
__device__ float g_Y  [(size_t)NMAX * 128];     // [h1@W2_self + b2 | h1@W2_neigh]
__device__ float g_W1 [128 * 256];              // cat(W1_self, W1_neigh)
__device__ float g_W2 [128 * 128];              // cat(W2_self, W2_neigh)
__device__ float g_b1 [256];                    // cat(b1, 0)
__device__ float g_b2 [128];                    // cat(b2, 0)

// ---------------- small prep kernels ----------------
__global__ void k_zero(int N) {
    int i = blockIdx.x * blockDim.x + threadIdx.x;
    if (i < N) { g_deg[i] = 0; g_cursor[i] = 0; g_flag[i] = 0; }
}

__global__ void k_prep(const float* __restrict__ W1s, const float* __restrict__ W1n,
                       const float* __restrict__ b1,
                       const float* __restrict__ W2s, const float* __restrict__ W2n,
                       const float* __restrict__ b2) {
    int i = blockIdx.x * blockDim.x + threadIdx.x;
    if (i < 128 * 256) {
        int k = i >> 8, j = i & 255;
        g_W1[i] = (j < 128) ? W1s[k * 128 + j] : W1n[k * 128 + (j - 128)];
    }
    int i2 = i - 128 * 256;
    if (i2 >= 0 && i2 < 128 * 128) {
        int k = i2 >> 7, j = i2 & 127;
        g_W2[i2] = (j < 64) ? W2s[k * 64 + j] : W2n[k * 64 + (j - 64)];
    }
    if (i < 256) g_b1[i] = (i < 128) ? b1[i] : 0.f;
    if (i < 128) g_b2[i] = (i < 64) ? b2[i] : 0.f;
}

__global__ void k_flags(const int* __restrict__ keep, int nk,
                        const int* __restrict__ low, int nl) {
    int i = blockIdx.x * blockDim.x + threadIdx.x;
    if (i < nk) g_flag[keep[i]] = 1;
    else if (i - nk < nl) g_flag[low[i - nk]] = 2;
}

__global__ void k_degcount(const int* __restrict__ dst, int E) {
    int i = blockIdx.x * blockDim.x + threadIdx.x;
    if (i < E) atomicAdd(&g_deg[dst[i]], 1);
}

// ---------------- parallel exclusive scan over degrees (3 kernels) ----------------
__global__ void k_scanA(int N) {
    int i = blockIdx.x * 1024 + threadIdx.x;
    int v = (i < N) ? g_deg[i] : 0;
    #pragma unroll
    for (int o = 16; o; o >>= 1) v += __shfl_down_sync(0xffffffffu, v, o);
    __shared__ int ws[32];
    if ((threadIdx.x & 31) == 0) ws[threadIdx.x >> 5] = v;
    __syncthreads();
    if (threadIdx.x < 32) {
        int s = ws[threadIdx.x];
        #pragma unroll
        for (int o = 16; o; o >>= 1) s += __shfl_down_sync(0xffffffffu, s, o);
        if (threadIdx.x == 0) g_part[blockIdx.x] = s;
    }
}

__global__ void k_scanB(int nb, int N, int E) {
    __shared__ int sm[128];
    int t = threadIdx.x;
    int v = (t < nb) ? g_part[t] : 0;
    sm[t] = v;
    __syncthreads();
    #pragma unroll
    for (int o = 1; o < 128; o <<= 1) {
        int u = 0;
        if (t >= o) u = sm[t - o];
        __syncthreads();
        sm[t] += u;
        __syncthreads();
    }
    g_part[t] = sm[t] - v;   // exclusive
    if (t == 0) g_rowptr[N] = E;
}

__global__ void k_scanC(int N) {
    int i = blockIdx.x * 1024 + threadIdx.x;
    int d = (i < N) ? g_deg[i] : 0;
    int lane = threadIdx.x & 31, w = threadIdx.x >> 5;
    int x = d;
    #pragma unroll
    for (int o = 1; o < 32; o <<= 1) {
        int y = __shfl_up_sync(0xffffffffu, x, o);
        if (lane >= o) x += y;
    }
    __shared__ int ws[32];
    if (lane == 31) ws[w] = x;
    __syncthreads();
    if (w == 0) {
        int s = ws[lane];
        #pragma unroll
        for (int o = 1; o < 32; o <<= 1) {
            int y = __shfl_up_sync(0xffffffffu, s, o);
            if (lane >= o) s += y;
        }
        ws[lane] = s;
    }
    __syncthreads();
    int excl = x - d + (w ? ws[w - 1] : 0) + g_part[blockIdx.x];
    if (i < N) {
        g_rowptr[i] = excl;
        g_deginv[i] = 1.0f / (float)((d > 1) ? d : 1);
    }
}

__global__ void k_bin(const int* __restrict__ src, const int* __restrict__ dst, int E) {
    int i = blockIdx.x * blockDim.x + threadIdx.x;
    if (i < E) {
        int d = dst[i];
        int p = atomicAdd(&g_cursor[d], 1);
        g_esrc[g_rowptr[d] + p] = src[i];
    }
}

// ---------------- tf32 tensor-core GEMM ----------------
// Y[M x NCOLS] = X[M x 128] @ W[128 x NCOLS] + bias
// Block = 64 rows, loops bn over all NCOLS (A tile resident -> X read once).
#define AS_STRIDE 132   // 128 + 4  -> conflict-free A reads
#define BS_STRIDE 72    // 64 + 8   -> conflict-free B reads

__device__ __forceinline__ uint32_t f2tf32(float f) {
    uint32_t r;
    asm("cvt.rna.tf32.f32 %0, %1;" : "=r"(r) : "f"(f));
    return r;
}

template <int NCOLS>
__global__ void __launch_bounds__(128, 3) k_gemm_tc(const float* __restrict__ Xext, int M) {
    extern __shared__ uint32_t sm[];
    uint32_t* As = sm;                       // 64 x AS_STRIDE (tf32 bits)
    uint32_t* Bs = sm + 64 * AS_STRIDE;      // 128 x BS_STRIDE (tf32 bits)
    const float* X    = (NCOLS == 256) ? Xext : g_h1;
    const float* W    = (NCOLS == 256) ? g_W1 : g_W2;
    const float* bias = (NCOLS == 256) ? g_b1 : g_b2;
    float* Y          = (NCOLS == 256) ? g_XY1 : g_Y;

    int bm = blockIdx.x * 64;
    int tid = threadIdx.x;
    int wid = tid >> 5, lane = tid & 31;
    int g = lane >> 2, t = lane & 3;
    int wm = wid >> 1, wn = wid & 1;         // 2x2 warp grid over 64x64

    // stage A once: 64 rows x 128 cols
    #pragma unroll
    for (int i = 0; i < 16; i++) {
        int idx = tid + i * 128;             // 0..2047
        int r = idx >> 5, c4 = (idx & 31) << 2;
        int row = bm + r;
        float4 v = (row < M) ? *(const float4*)&X[(size_t)row * 128 + c4]
                             : make_float4(0.f, 0.f, 0.f, 0.f);
        uint32_t* d = &As[r * AS_STRIDE + c4];
        d[0] = f2tf32(v.x); d[1] = f2tf32(v.y); d[2] = f2tf32(v.z); d[3] = f2tf32(v.w);
    }

    for (int bn = 0; bn < NCOLS; bn += 64) {
        __syncthreads();   // prior compute done (and As ready on first iter)
        #pragma unroll
        for (int i = 0; i < 16; i++) {
            int idx = tid + i * 128;
            int k = idx >> 4, c4 = (idx & 15) << 2;
            float4 v = *(const float4*)&W[k * NCOLS + bn + c4];
            uint32_t* d = &Bs[k * BS_STRIDE + c4];
            d[0] = f2tf32(v.x); d[1] = f2tf32(v.y); d[2] = f2tf32(v.z); d[3] = f2tf32(v.w);
        }
        __syncthreads();

        float c[2][4][4];
        #pragma unroll
        for (int mt = 0; mt < 2; mt++)
            #pragma unroll
            for (int nt = 0; nt < 4; nt++)
                #pragma unroll
                for (int q = 0; q < 4; q++) c[mt][nt][q] = 0.f;

        #pragma unroll 4
        for (int k0 = 0; k0 < 128; k0 += 8) {
            uint32_t a[2][4];
            #pragma unroll
            for (int mt = 0; mt < 2; mt++) {
                int rb = (wm * 32 + mt * 16 + g) * AS_STRIDE;
                a[mt][0] = As[rb + k0 + t];
                a[mt][1] = As[rb + 8 * AS_STRIDE + k0 + t];
                a[mt][2] = As[rb + k0 + t + 4];
                a[mt][3] = As[rb + 8 * AS_STRIDE + k0 + t + 4];
            }
            uint32_t b[4][2];
            #pragma unroll
            for (int nt = 0; nt < 4; nt++) {
                int col = wn * 32 + nt * 8 + g;
                b[nt][0] = Bs[(k0 + t) * BS_STRIDE + col];
                b[nt][1] = Bs[(k0 + t + 4) * BS_STRIDE + col];
            }
            #pragma unroll
            for (int mt = 0; mt < 2; mt++)
                #pragma unroll
                for (int nt = 0; nt < 4; nt++) {
                    asm volatile(
                        "mma.sync.aligned.m16n8k8.row.col.f32.tf32.tf32.f32 "
                        "{%0,%1,%2,%3}, {%4,%5,%6,%7}, {%8,%9}, {%0,%1,%2,%3};"
                        : "+f"(c[mt][nt][0]), "+f"(c[mt][nt][1]),
                          "+f"(c[mt][nt][2]), "+f"(c[mt][nt][3])
                        : "r"(a[mt][0]), "r"(a[mt][1]), "r"(a[mt][2]), "r"(a[mt][3]),
                          "r"(b[nt][0]), "r"(b[nt][1]));
                }
        }

        // epilogue for this bn chunk
        #pragma unroll
        for (int mt = 0; mt < 2; mt++) {
            int row = bm + wm * 32 + mt * 16 + g;
            #pragma unroll
            for (int nt = 0; nt < 4; nt++) {
                int col = bn + wn * 32 + nt * 8 + 2 * t;
                float2 bv = *(const float2*)&bias[col];
                if (row < M) {
                    float2 o0 = make_float2(c[mt][nt][0] + bv.x, c[mt][nt][1] + bv.y);
                    *(float2*)&Y[(size_t)row * NCOLS + col] = o0;
                }
                if (row + 8 < M) {
                    float2 o1 = make_float2(c[mt][nt][2] + bv.x, c[mt][nt][3] + bv.y);
                    *(float2*)&Y[(size_t)(row + 8) * NCOLS + col] = o1;
                }
            }
        }
    }
}

// ---------------- layer-1 aggregation: warp per node, MLP-4 ----------------
__global__ void k_agg1(int N) {
    int w = (blockIdx.x * blockDim.x + threadIdx.x) >> 5;
    int lane = threadIdx.x & 31;
    if (w >= N) return;
    int beg = g_rowptr[w], end = g_rowptr[w + 1];
    float ax = 0.f, ay = 0.f, az = 0.f, aw = 0.f;
    int col = 128 + lane * 4;
    int j = beg;
    for (; j + 3 < end; j += 4) {
        int s0 = g_esrc[j],     s1 = g_esrc[j + 1];
        int s2 = g_esrc[j + 2], s3 = g_esrc[j + 3];
        float4 v0 = *(const float4*)&g_XY1[s0 * 256 + col];
        float4 v1 = *(const float4*)&g_XY1[s1 * 256 + col];
        float4 v2 = *(const float4*)&g_XY1[s2 * 256 + col];
        float4 v3 = *(const float4*)&g_XY1[s3 * 256 + col];
        ax += (v0.x + v1.x) + (v2.x + v3.x);
        ay += (v0.y + v1.y) + (v2.y + v3.y);
        az += (v0.z + v1.z) + (v2.z + v3.z);
        aw += (v0.w + v1.w) + (v2.w + v3.w);
    }
    for (; j < end; j++) {
        int s0 = g_esrc[j];
        float4 v0 = *(const float4*)&g_XY1[s0 * 256 + col];
        ax += v0.x; ay += v0.y; az += v0.z; aw += v0.w;
    }
    float di = g_deginv[w];
    float4 xs = *(const float4*)&g_XY1[w * 256 + lane * 4];
    float4 h;
    h.x = fmaxf(fmaf(ax, di, xs.x), 0.f);
    h.y = fmaxf(fmaf(ay, di, xs.y), 0.f);
    h.z = fmaxf(fmaf(az, di, xs.z), 0.f);
    h.w = fmaxf(fmaf(aw, di, xs.w), 0.f);
    *(float4*)&g_h1[w * 128 + lane * 4] = h;
}

// ---------------- layer-2 aggregation + final select: warp per node ----------------
__global__ void k_final(const float* __restrict__ emb, float* __restrict__ out, int N) {
    int w = (blockIdx.x * blockDim.x + threadIdx.x) >> 5;
    int lane = threadIdx.x & 31;
    if (w >= N) return;
    unsigned char f = g_flag[w];
    if (f == 1) {   // keep: pure embedding copy, skip all layer-2 work
        float2 e = *(const float2*)&emb[(size_t)w * 64 + lane * 2];
        *(float2*)&out[(size_t)w * 64 + lane * 2] = e;
        return;
    }
    int beg = g_rowptr[w], end = g_rowptr[w + 1];
    float ax = 0.f, ay = 0.f;
    int col = 64 + lane * 2;
    int j = beg;
    for (; j + 3 < end; j += 4) {
        int s0 = g_esrc[j],     s1 = g_esrc[j + 1];
        int s2 = g_esrc[j + 2], s3 = g_esrc[j + 3];
        float2 v0 = *(const float2*)&g_Y[s0 * 128 + col];
        float2 v1 = *(const float2*)&g_Y[s1 * 128 + col];
        float2 v2 = *(const float2*)&g_Y[s2 * 128 + col];
        float2 v3 = *(const float2*)&g_Y[s3 * 128 + col];
        ax += (v0.x + v1.x) + (v2.x + v3.x);
        ay += (v0.y + v1.y) + (v2.y + v3.y);
    }
    for (; j < end; j++) {
        int s0 = g_esrc[j];
        float2 v0 = *(const float2*)&g_Y[s0 * 128 + col];
        ax += v0.x; ay += v0.y;
    }
    float di = g_deginv[w];
    float2 ys = *(const float2*)&g_Y[w * 128 + lane * 2];
    float sc = (f == 2) ? 2.f : 1.f;
    float2 o;
    o.x = (ys.x + ax * di) * sc;
    o.y = (ys.y + ay * di) * sc;
    *(float2*)&out[(size_t)w * 64 + lane * 2] = o;
}

// ---------------- launch ----------------
extern "C" void kernel_launch(void* const* d_in, const int* in_sizes, int n_in,
                              void* d_out, int out_size) {
    const float* features = (const float*)d_in[0];
    const float* W1s = (const float*)d_in[1];
    const float* W1n = (const float*)d_in[2];
    const float* b1  = (const float*)d_in[3];
    const float* W2s = (const float*)d_in[4];
    const float* W2n = (const float*)d_in[5];
    const float* b2  = (const float*)d_in[6];
    const float* emb = (const float*)d_in[7];
    const int* src   = (const int*)d_in[8];
    const int* dst   = (const int*)d_in[9];
    const int* keep  = (const int*)d_in[10];
    const int* low   = (const int*)d_in[11];

    int N  = in_sizes[0] / 128;
    int E  = in_sizes[8];
    int nk = in_sizes[10];
    int nl = in_sizes[11];
    float* out = (float*)d_out;

    static cudaStream_t s2 = nullptr;
    static cudaEvent_t ev_fork = nullptr, ev_join = nullptr;
    if (!s2) {
        cudaStreamCreateWithFlags(&s2, cudaStreamNonBlocking);
        cudaEventCreateWithFlags(&ev_fork, cudaEventDisableTiming);
        cudaEventCreateWithFlags(&ev_join, cudaEventDisableTiming);
    }

    const int smem_bytes = (64 * AS_STRIDE + 128 * BS_STRIDE) * 4;  // 70656
    cudaFuncSetAttribute(k_gemm_tc<256>, cudaFuncAttributeMaxDynamicSharedMemorySize, smem_bytes);
    cudaFuncSetAttribute(k_gemm_tc<128>, cudaFuncAttributeMaxDynamicSharedMemorySize, smem_bytes);

    int nb = (N + 1023) / 1024;   // scan blocks (<=128)

    // stream 0: zero, then fork CSR build onto s2
    k_zero<<<(N + 255) / 256, 256>>>(N);
    cudaEventRecord(ev_fork, 0);
    cudaStreamWaitEvent(s2, ev_fork, 0);

    // s2: CSR build chain (independent of GEMM1)
    k_degcount<<<(E + 255) / 256, 256, 0, s2>>>(dst, E);
    k_scanA<<<nb, 1024, 0, s2>>>(N);
    k_scanB<<<1, 128, 0, s2>>>(nb, N, E);
    k_scanC<<<nb, 1024, 0, s2>>>(N);
    k_bin<<<(E + 255) / 256, 256, 0, s2>>>(src, dst, E);
    cudaEventRecord(ev_join, s2);

    // stream 0 meanwhile: weights prep, flags, GEMM1
    k_prep<<<(128 * 256 + 128 * 128 + 255) / 256, 256>>>(W1s, W1n, b1, W2s, W2n, b2);
    k_flags<<<(nk + nl + 255) / 256, 256>>>(keep, nk, low, nl);
    k_gemm_tc<256><<<(N + 63) / 64, 128, smem_bytes>>>(features, N);

    // join: agg needs CSR + XY1
    cudaStreamWaitEvent(0, ev_join, 0);
    k_agg1<<<(N + 7) / 8, 256>>>(N);
    k_gemm_tc<128><<<(N + 63) / 64, 128, smem_bytes>>>(nullptr, N);
    k_final<<<(N + 7) / 8, 256>>>(emb, out, N);
}